// round 2
// baseline (speedup 1.0000x reference)
#include <cuda_runtime.h>
#include <math.h>

#define B_  128
#define S_  128
#define W_  16
#define V_  128
#define H_  512
#define G3_ 1536
#define L_  64

// ---------------- scratch (device globals; no allocation) ----------------
__device__ float g_x  [B_*S_*V_];        // FOFE output x[b][s][v]        (8 MB)
__device__ float g_xw [2*S_*B_*G3_];     // xw[dir][t][b][g] (incl b_ih)  (201 MB)
__device__ float g_h  [2*B_*H_];         // hidden state per dir          (0.5 MB)
__device__ float g_hwp[2*4*B_*G3_];      // K-split partial h@W_hh^T      (6.3 MB)
__device__ float g_gru[2*S_*B_*H_];      // out_f / out_b_rev [dir][t][b] (67 MB)
__device__ float g_cat[B_*S_*2*H_];      // concat rows for final GEMM    (67 MB)

// ---------------- init hidden state (must re-zero every replay) -----------
__global__ void k_zero_h() {
    int i = blockIdx.x * blockDim.x + threadIdx.x;
    if (i < 2*B_*H_) g_h[i] = 0.f;
}

// ---------------- FOFE encoding ----------------
__global__ void k_fofe(const int* __restrict__ chars, const float* __restrict__ forget_p) {
    int bs = blockIdx.x;                  // b*S + s
    __shared__ int   c[W_];
    __shared__ float wt[W_];
    int tid = threadIdx.x;                // 128 threads = V
    if (tid < W_) c[tid] = chars[bs*W_ + tid];
    __syncthreads();
    if (tid < W_) {
        int cnt = 0;
        for (int w = tid + 1; w < W_; ++w) cnt += (c[w] != 0);
        wt[tid] = (c[tid] != 0) ? powf(forget_p[0], (float)cnt) : 0.f;
    }
    __syncthreads();
    float acc = 0.f;
#pragma unroll
    for (int w = 0; w < W_; ++w) acc += (c[w] == tid) ? wt[w] : 0.f;
    g_x[bs*V_ + tid] = acc;
}

// ---------------- xw = x @ W_ih^T + b_ih, both directions ----------------
// C rows r = t*B + b (dir1 rows gather reversed x). Tile 64x64, K=128.
__global__ void k_xw(const float* __restrict__ Wf, const float* __restrict__ Wb,
                     const float* __restrict__ bf, const float* __restrict__ bb,
                     const int*   __restrict__ lengths) {
    const int dir = blockIdx.z;
    const float* Wih = dir ? Wb : Wf;
    const float* bih = dir ? bb : bf;
    __shared__ float Xs[32][64];
    __shared__ float Ws[32][64];
    __shared__ const float* rowsrc[64];
    const int tid = threadIdx.x;
    const int r0 = blockIdx.y * 64;
    const int g0 = blockIdx.x * 64;
    if (tid < 64) {
        int r = r0 + tid;
        int t = r >> 7, b = r & 127;
        int s = t;
        if (dir) { s = lengths[b] - 1 - t; if (s < 0) s = 0; }
        rowsrc[tid] = g_x + (b*S_ + s)*V_;
    }
    __syncthreads();
    float acc[4][4] = {};
    const int ty = tid >> 4, tx = tid & 15;
    const int li = tid & 63, kq = tid >> 6;          // loader mapping
    for (int k0 = 0; k0 < V_; k0 += 32) {
        const float* xs = rowsrc[li] + k0 + kq*8;
        const float* ws = Wih + (g0 + li)*V_ + k0 + kq*8;
#pragma unroll
        for (int u = 0; u < 8; ++u) { Xs[kq*8+u][li] = xs[u]; Ws[kq*8+u][li] = ws[u]; }
        __syncthreads();
#pragma unroll
        for (int kk = 0; kk < 32; ++kk) {
            float a[4], w[4];
            *(float4*)a = *(const float4*)&Xs[kk][ty*4];
            *(float4*)w = *(const float4*)&Ws[kk][tx*4];
#pragma unroll
            for (int ii = 0; ii < 4; ++ii)
#pragma unroll
                for (int jj = 0; jj < 4; ++jj) acc[ii][jj] += a[ii]*w[jj];
        }
        __syncthreads();
    }
#pragma unroll
    for (int ii = 0; ii < 4; ++ii) {
        int r = r0 + ty*4 + ii;
        float* dst = g_xw + (dir*S_*B_ + r)*G3_ + g0;
#pragma unroll
        for (int jj = 0; jj < 4; ++jj) {
            int j = tx*4 + jj;
            dst[j] = acc[ii][jj] + bih[g0 + j];
        }
    }
}

// ---------------- per-step: hw partials = h @ W_hh^T (K-split 4) ----------
// grid (12 gtiles of 128, 4 k-splits of 128, 2 dirs). Tile 128x128, K=128.
__global__ void k_hh(const float* __restrict__ Whf, const float* __restrict__ Whb) {
    const int g0  = blockIdx.x * 128;
    const int ks  = blockIdx.y;
    const int dir = blockIdx.z;
    const float* Whh = dir ? Whb : Whf;
    __shared__ float Hs[32][128];
    __shared__ float Ws[32][128];
    const int tid = threadIdx.x;
    const int ty = tid >> 4, tx = tid & 15;
    const int li = tid & 127, kq = tid >> 7;         // kq 0..1, 16 k each
    float acc[8][8] = {};
    const float* hbase = g_h + dir*B_*H_;
    for (int k0 = ks*128; k0 < ks*128 + 128; k0 += 32) {
        const float* hs = hbase + li*H_ + k0 + kq*16;
        const float* ws = Whh + (g0 + li)*H_ + k0 + kq*16;
#pragma unroll
        for (int u = 0; u < 16; ++u) { Hs[kq*16+u][li] = hs[u]; Ws[kq*16+u][li] = ws[u]; }
        __syncthreads();
#pragma unroll 4
        for (int kk = 0; kk < 32; ++kk) {
            float a[8], w[8];
            *(float4*)&a[0] = *(const float4*)&Hs[kk][ty*8];
            *(float4*)&a[4] = *(const float4*)&Hs[kk][ty*8+4];
            *(float4*)&w[0] = *(const float4*)&Ws[kk][tx*8];
            *(float4*)&w[4] = *(const float4*)&Ws[kk][tx*8+4];
#pragma unroll
            for (int ii = 0; ii < 8; ++ii)
#pragma unroll
                for (int jj = 0; jj < 8; ++jj) acc[ii][jj] += a[ii]*w[jj];
        }
        __syncthreads();
    }
    float* dst = g_hwp + ((dir*4 + ks)*B_)*G3_;
#pragma unroll
    for (int ii = 0; ii < 8; ++ii) {
        int b = ty*8 + ii;
#pragma unroll
        for (int jj = 0; jj < 8; jj += 4)
            *(float4*)&dst[b*G3_ + g0 + tx*8 + jj] = *(const float4*)&acc[ii][jj];
    }
}

// ---------------- per-step: gates + state update + output -----------------
__global__ void k_gates(const float* __restrict__ bhf, const float* __restrict__ bhb,
                        const int* __restrict__ lengths, int t) {
    const int b = blockIdx.x, dir = blockIdx.y;
    const int j = threadIdx.x;                        // 512 threads = H
    const float* bhh = dir ? bhb : bhf;
    float hr = bhh[j], hz = bhh[H_ + j], hn = bhh[2*H_ + j];
#pragma unroll
    for (int ks = 0; ks < 4; ++ks) {
        const float* p = g_hwp + ((dir*4 + ks)*B_ + b)*G3_;
        hr += p[j]; hz += p[H_ + j]; hn += p[2*H_ + j];
    }
    const float* xw = g_xw + (dir*S_*B_ + t*B_ + b)*G3_;
    float r = 1.f/(1.f + expf(-(xw[j]      + hr)));
    float z = 1.f/(1.f + expf(-(xw[H_+j]   + hz)));
    float n = tanhf(xw[2*H_+j] + r*hn);
    float* hp = g_h + (dir*B_ + b)*H_ + j;
    float hold = *hp;
    float hnew = (1.f - z)*n + z*hold;
    bool m = (t < lengths[b]);
    g_gru[((dir*S_ + t)*B_ + b)*H_ + j] = m ? hnew : 0.f;
    if (m) *hp = hnew;
}

// ---------------- gather/concat rows for final linear ---------------------
__global__ void k_cat(const int* __restrict__ lengths) {
    const int s = blockIdx.x, b = blockIdx.y;
    const int len = lengths[b];
    float* dst = g_cat + (b*S_ + s)*(2*H_);
    for (int j = threadIdx.x; j < 2*H_; j += blockDim.x) {
        float v;
        if (j < H_)            v = g_gru[(s*B_ + b)*H_ + j];
        else if (s < len)      v = g_gru[((S_ + (len-1-s))*B_ + b)*H_ + (j - H_)];
        else                   v = 0.f;
        dst[j] = v;
    }
}

// ---------------- final linear: out = cat @ W_lin^T + b_lin ---------------
// M=16384 rows (b*S+s), N=64, K=1024. Tile 64x64.
__global__ void k_lin(const float* __restrict__ Wlin, const float* __restrict__ blin,
                      float* __restrict__ out) {
    __shared__ float Xs[32][64];
    __shared__ float Ws[32][64];
    const int tid = threadIdx.x;
    const int r0 = blockIdx.x * 64;
    const int ty = tid >> 4, tx = tid & 15;
    const int li = tid & 63, kq = tid >> 6;
    float acc[4][4] = {};
    for (int k0 = 0; k0 < 2*H_; k0 += 32) {
        const float* xs = g_cat + (r0 + li)*(2*H_) + k0 + kq*8;
        const float* ws = Wlin + li*(2*H_) + k0 + kq*8;
#pragma unroll
        for (int u = 0; u < 8; ++u) { Xs[kq*8+u][li] = xs[u]; Ws[kq*8+u][li] = ws[u]; }
        __syncthreads();
#pragma unroll
        for (int kk = 0; kk < 32; ++kk) {
            float a[4], w[4];
            *(float4*)a = *(const float4*)&Xs[kk][ty*4];
            *(float4*)w = *(const float4*)&Ws[kk][tx*4];
#pragma unroll
            for (int ii = 0; ii < 4; ++ii)
#pragma unroll
                for (int jj = 0; jj < 4; ++jj) acc[ii][jj] += a[ii]*w[jj];
        }
        __syncthreads();
    }
#pragma unroll
    for (int ii = 0; ii < 4; ++ii) {
        int r = r0 + ty*4 + ii;
#pragma unroll
        for (int jj = 0; jj < 4; ++jj) {
            int l = tx*4 + jj;
            out[r*L_ + l] = acc[ii][jj] + blin[l];
        }
    }
}

// ---------------- launch ----------------
extern "C" void kernel_launch(void* const* d_in, const int* in_sizes, int n_in,
                              void* d_out, int out_size) {
    const int*   chars   = (const int*)  d_in[0];
    const int*   lengths = (const int*)  d_in[1];
    const float* forget  = (const float*)d_in[2];
    const float* W_ih_f  = (const float*)d_in[3];
    const float* W_hh_f  = (const float*)d_in[4];
    const float* b_ih_f  = (const float*)d_in[5];
    const float* b_hh_f  = (const float*)d_in[6];
    const float* W_ih_b  = (const float*)d_in[7];
    const float* W_hh_b  = (const float*)d_in[8];
    const float* b_ih_b  = (const float*)d_in[9];
    const float* b_hh_b  = (const float*)d_in[10];
    const float* W_lin   = (const float*)d_in[11];
    const float* b_lin   = (const float*)d_in[12];
    float* out = (float*)d_out;

    k_zero_h<<<(2*B_*H_ + 255)/256, 256>>>();
    k_fofe  <<<B_*S_, V_>>>(chars, forget);
    k_xw    <<<dim3(G3_/64, (S_*B_)/64, 2), 256>>>(W_ih_f, W_ih_b, b_ih_f, b_ih_b, lengths);
    for (int t = 0; t < S_; ++t) {
        k_hh   <<<dim3(12, 4, 2), 256>>>(W_hh_f, W_hh_b);
        k_gates<<<dim3(B_, 2), H_>>>(b_hh_f, b_hh_b, lengths, t);
    }
    k_cat<<<dim3(S_, B_), 256>>>(lengths);
    k_lin<<<(S_*B_)/64, 256>>>(W_lin, b_lin, out);
}

// round 6
// speedup vs baseline: 2.1084x; 2.1084x over previous
#include <cuda_runtime.h>
#include <cuda_bf16.h>
#include <math.h>
#include <stdint.h>

#define B_  128
#define S_  128
#define W_  16
#define V_  128
#define H_  512
#define G3_ 1536
#define L_  64

// k_step smem layout
#define WPSZ  49920                    // 48 rows x 1040B per precision
#define OFF_W 0                        // 2 prec -> 99840
#define ASZ   17408                    // 64 rows x 272B
#define OFF_A 99840                    // [buf][prec] x 17408 -> 69632
#define OFF_C 169472                   // 48 x 68 fp32 = 13056
#define STEP_SMEM 182528

// ---------------- scratch (device globals; no allocation) ----------------
__device__ float g_x  [B_*S_*V_];
__device__ float g_xw [(size_t)2*S_*B_*G3_];          // [dir][t*B+b][g] incl b_ih
__device__ float g_h32[2][B_][H_];                    // exact fp32 hidden state
__device__ __nv_bfloat16 g_hbf[2][2][2][B_][H_];      // [parity][dir][prec][b][k]
__device__ __nv_bfloat16 g_wp [2][2][G3_][H_];        // [prec][dir][perm row][k]
__device__ float g_gru[(size_t)2*S_*B_*H_];
__device__ float g_cat[(size_t)B_*S_*2*H_];

// ---------------- helpers ----------------
__device__ __forceinline__ uint32_t s2u(const void* p){
    uint32_t a;
    asm("{ .reg .u64 t; cvta.to.shared.u64 t, %1; cvt.u32.u64 %0, t; }" : "=r"(a) : "l"(p));
    return a;
}
__device__ __forceinline__ void ldsm4(uint32_t* r, uint32_t a){
    asm volatile("ldmatrix.sync.aligned.m8n8.x4.shared.b16 {%0,%1,%2,%3}, [%4];"
        : "=r"(r[0]), "=r"(r[1]), "=r"(r[2]), "=r"(r[3]) : "r"(a));
}
__device__ __forceinline__ void ldsm2(uint32_t* r, uint32_t a){
    asm volatile("ldmatrix.sync.aligned.m8n8.x2.shared.b16 {%0,%1}, [%2];"
        : "=r"(r[0]), "=r"(r[1]) : "r"(a));
}
__device__ __forceinline__ void mma16816(float* c, const uint32_t* a, const uint32_t* b){
    asm volatile("mma.sync.aligned.m16n8k16.row.col.f32.bf16.bf16.f32 "
        "{%0,%1,%2,%3}, {%4,%5,%6,%7}, {%8,%9}, {%0,%1,%2,%3};"
        : "+f"(c[0]), "+f"(c[1]), "+f"(c[2]), "+f"(c[3])
        : "r"(a[0]), "r"(a[1]), "r"(a[2]), "r"(a[3]), "r"(b[0]), "r"(b[1]));
}
__device__ __forceinline__ void cpa16(uint32_t dst, const void* src){
    asm volatile("cp.async.cg.shared.global [%0], [%1], 16;" :: "r"(dst), "l"(src));
}

// ---------------- init (re-run every replay) ----------------
__global__ void k_zero(){
    int i = blockIdx.x * 256 + threadIdx.x;
    if (i < 2*B_*H_) ((float*)g_h32)[i] = 0.f;
    if (i < 4*B_*H_) ((uint32_t*)g_hbf)[i] = 0u;   // 2par*2dir*2prec*B*H bf16 = 262144 u32
}

// ---------------- permute + split W_hh into bf16 hi/lo --------------------
__global__ void k_prep(const float* __restrict__ Wf, const float* __restrict__ Wb){
    int e = blockIdx.x * 256 + threadIdx.x;
    if (e >= 2*G3_*H_) return;
    int dir = e / (G3_*H_);
    int rem = e - dir*(G3_*H_);
    int ro  = rem / H_;
    int k   = rem % H_;
    int u = ro / 3, g = ro % 3;
    float w = (dir ? Wb : Wf)[(g*H_ + u)*H_ + k];
    __nv_bfloat16 hi = __float2bfloat16(w);
    __nv_bfloat16 lo = __float2bfloat16(w - __bfloat162float(hi));
    g_wp[0][dir][ro][k] = hi;
    g_wp[1][dir][ro][k] = lo;
}

// ---------------- FOFE ----------------
__global__ void k_fofe(const int* __restrict__ chars, const float* __restrict__ forget_p) {
    int bs = blockIdx.x;
    __shared__ int   c[W_];
    __shared__ float wt[W_];
    int tid = threadIdx.x;
    if (tid < W_) c[tid] = chars[bs*W_ + tid];
    __syncthreads();
    if (tid < W_) {
        int cnt = 0;
        for (int w = tid + 1; w < W_; ++w) cnt += (c[w] != 0);
        wt[tid] = (c[tid] != 0) ? powf(forget_p[0], (float)cnt) : 0.f;
    }
    __syncthreads();
    float acc = 0.f;
#pragma unroll
    for (int w = 0; w < W_; ++w) acc += (c[w] == tid) ? wt[w] : 0.f;
    g_x[bs*V_ + tid] = acc;
}

// ---------------- xw = x @ W_ih^T + b_ih ----------------
__global__ void k_xw(const float* __restrict__ Wf, const float* __restrict__ Wb,
                     const float* __restrict__ bf, const float* __restrict__ bb,
                     const int*   __restrict__ lengths) {
    const int dir = blockIdx.z;
    const float* Wih = dir ? Wb : Wf;
    const float* bih = dir ? bb : bf;
    __shared__ float Xs[32][64];
    __shared__ float Ws[32][64];
    __shared__ const float* rowsrc[64];
    const int tid = threadIdx.x;
    const int r0 = blockIdx.y * 64;
    const int g0 = blockIdx.x * 64;
    if (tid < 64) {
        int r = r0 + tid;
        int t = r >> 7, b = r & 127;
        int s = t;
        if (dir) { s = lengths[b] - 1 - t; if (s < 0) s = 0; }
        rowsrc[tid] = g_x + (b*S_ + s)*V_;
    }
    __syncthreads();
    float acc[4][4] = {};
    const int ty = tid >> 4, tx = tid & 15;
    const int li = tid & 63, kq = tid >> 6;
    for (int k0 = 0; k0 < V_; k0 += 32) {
        const float* xs = rowsrc[li] + k0 + kq*8;
        const float* ws = Wih + (g0 + li)*V_ + k0 + kq*8;
#pragma unroll
        for (int u = 0; u < 8; ++u) { Xs[kq*8+u][li] = xs[u]; Ws[kq*8+u][li] = ws[u]; }
        __syncthreads();
#pragma unroll
        for (int kk = 0; kk < 32; ++kk) {
            float a[4], w[4];
            *(float4*)a = *(const float4*)&Xs[kk][ty*4];
            *(float4*)w = *(const float4*)&Ws[kk][tx*4];
#pragma unroll
            for (int ii = 0; ii < 4; ++ii)
#pragma unroll
                for (int jj = 0; jj < 4; ++jj) acc[ii][jj] += a[ii]*w[jj];
        }
        __syncthreads();
    }
#pragma unroll
    for (int ii = 0; ii < 4; ++ii) {
        int r = r0 + ty*4 + ii;
        float* dst = g_xw + ((size_t)dir*S_*B_ + r)*G3_ + g0;
#pragma unroll
        for (int jj = 0; jj < 4; ++jj) {
            int j = tx*4 + jj;
            dst[j] = acc[ii][jj] + bih[g0 + j];
        }
    }
}

// ---------------- fused per-step: HMMA (3-term split bf16) + gates --------
__global__ void __launch_bounds__(256)
k_step(const int* __restrict__ lengths, const float* __restrict__ bhf,
       const float* __restrict__ bhb, int t){
    extern __shared__ char sm[];
    const uint32_t sb = s2u(sm);
    const int tid  = threadIdx.x;
    const int lane = tid & 31;
    const int wid  = tid >> 5;
    const int wm = wid & 3, wn = wid >> 2;           // m-tile 16, n-half 24
    const int cu = blockIdx.x, bh = blockIdx.y, dir = blockIdx.z;
    const int par = t & 1;

    // W slice: 2 prec x 48 rows x 512 k, row stride 1040B
    for (int i = tid; i < 6144; i += 256){
        int p = i / 3072, j = i % 3072;
        int row = j >> 6, seg = j & 63;
        cpa16(sb + OFF_W + p*WPSZ + row*1040 + seg*16,
              &g_wp[p][dir][cu*48 + row][seg*8]);
    }
    asm volatile("cp.async.commit_group;");
    // h chunks 0,1
#pragma unroll
    for (int c = 0; c < 2; ++c){
#pragma unroll
        for (int p = 0; p < 2; ++p)
#pragma unroll
            for (int j = 0; j < 4; ++j){
                int i = tid + j*256;
                int row = i >> 4, seg = i & 15;
                cpa16(sb + OFF_A + (c*2 + p)*ASZ + row*272 + seg*16,
                      &g_hbf[par][dir][p][bh*64 + row][c*128 + seg*8]);
            }
        asm volatile("cp.async.commit_group;");
    }

    const int ln = lane & 15;
    const uint32_t aoff = (uint32_t)(wm*16 + (lane & 15))*272 + (uint32_t)(lane >> 4)*16;
    const uint32_t boffr = (uint32_t)(wn*24 + (ln & 7))*1040 + (uint32_t)(ln >> 3)*16;
    float acc[3][4] = {};

    for (int c = 0; c < 4; ++c){
        if (c < 3) asm volatile("cp.async.wait_group 1;");
        else       asm volatile("cp.async.wait_group 0;");
        __syncthreads();
        const int buf = c & 1;
        const uint32_t Ah = sb + OFF_A + (buf*2)*ASZ + aoff;
        const uint32_t Al = Ah + ASZ;
        const uint32_t Bb = sb + OFF_W + boffr + (uint32_t)c*256;
#pragma unroll
        for (int ks = 0; ks < 8; ++ks){
            uint32_t aH[4], aL[4];
            ldsm4(aH, Ah + ks*32);
            ldsm4(aL, Al + ks*32);
#pragma unroll
            for (int nt = 0; nt < 3; ++nt){
                uint32_t bH[2], bL[2];
                uint32_t ba = Bb + (uint32_t)nt*8*1040 + (uint32_t)ks*32;
                ldsm2(bH, ba);
                ldsm2(bL, ba + WPSZ);
                mma16816(acc[nt], aH, bH);
                mma16816(acc[nt], aL, bH);
                mma16816(acc[nt], aH, bL);
            }
        }
        __syncthreads();
        if (c < 2){
#pragma unroll
            for (int p = 0; p < 2; ++p)
#pragma unroll
                for (int j = 0; j < 4; ++j){
                    int i = tid + j*256;
                    int row = i >> 4, seg = i & 15;
                    cpa16(sb + OFF_A + (buf*2 + p)*ASZ + row*272 + seg*16,
                          &g_hbf[par][dir][p][bh*64 + row][(c+2)*128 + seg*8]);
                }
            asm volatile("cp.async.commit_group;");
        }
    }

    // stage C: Cs[n 48][m 64], stride 68
    float* Cs = (float*)(sm + OFF_C);
    {
        const int trow = lane >> 2, tcol = (lane & 3)*2;
#pragma unroll
        for (int nt = 0; nt < 3; ++nt){
            int n = wn*24 + nt*8 + tcol;
            int m = wm*16 + trow;
            Cs[n*68 + m]          = acc[nt][0];
            Cs[(n+1)*68 + m]      = acc[nt][1];
            Cs[n*68 + m + 8]      = acc[nt][2];
            Cs[(n+1)*68 + m + 8]  = acc[nt][3];
        }
    }
    __syncthreads();

    // gates + state update: thread = (bloc 0..63, ub 0..3) -> units ub*4..+3
    {
        const int bloc = tid & 63, ub = tid >> 6;
        const int bg = bh*64 + bloc;
        const bool msk = (t < lengths[bg]);
        const float* bhv = dir ? bhb : bhf;
        const float* xw = g_xw + ((size_t)(dir*S_ + t)*B_ + bg)*G3_;
        const int par2 = par ^ 1;
        const int ubase = cu*16 + ub*4;
        float gv[4], hv[4];
#pragma unroll
        for (int i = 0; i < 4; ++i){
            const int ul = ub*4 + i;
            const int u  = ubase + i;
            float pr = Cs[(ul*3+0)*68 + bloc] + bhv[u]        + xw[u];
            float pz = Cs[(ul*3+1)*68 + bloc] + bhv[H_ + u]   + xw[H_ + u];
            float pn = Cs[(ul*3+2)*68 + bloc] + bhv[2*H_ + u];
            float r = 1.f/(1.f + expf(-pr));
            float z = 1.f/(1.f + expf(-pz));
            float n = tanhf(xw[2*H_ + u] + r*pn);
            float hold = g_h32[dir][bg][u];
            float hnew = (1.f - z)*n + z*hold;
            gv[i] = msk ? hnew : 0.f;
            hv[i] = msk ? hnew : hold;
        }
        *(float4*)&g_gru[(((size_t)dir*S_ + t)*B_ + bg)*H_ + ubase] = *(float4*)gv;
        *(float4*)&g_h32[dir][bg][ubase] = *(float4*)hv;
        __nv_bfloat16 hi[4], lo[4];
#pragma unroll
        for (int i = 0; i < 4; ++i){
            hi[i] = __float2bfloat16(hv[i]);
            lo[i] = __float2bfloat16(hv[i] - __bfloat162float(hi[i]));
        }
        *(uint2*)&g_hbf[par2][dir][0][bg][ubase] = *(uint2*)hi;
        *(uint2*)&g_hbf[par2][dir][1][bg][ubase] = *(uint2*)lo;
    }
}

// ---------------- gather/concat rows for final linear ---------------------
__global__ void k_cat(const int* __restrict__ lengths) {
    const int s = blockIdx.x, b = blockIdx.y;
    const int len = lengths[b];
    float* dst = g_cat + ((size_t)b*S_ + s)*(2*H_);
    for (int j = threadIdx.x; j < 2*H_; j += blockDim.x) {
        float v;
        if (j < H_)            v = g_gru[((size_t)s*B_ + b)*H_ + j];
        else if (s < len)      v = g_gru[((size_t)(S_ + (len-1-s))*B_ + b)*H_ + (j - H_)];
        else                   v = 0.f;
        dst[j] = v;
    }
}

// ---------------- final linear ----------------
__global__ void k_lin(const float* __restrict__ Wlin, const float* __restrict__ blin,
                      float* __restrict__ out) {
    __shared__ float Xs[32][64];
    __shared__ float Ws[32][64];
    const int tid = threadIdx.x;
    const int r0 = blockIdx.x * 64;
    const int ty = tid >> 4, tx = tid & 15;
    const int li = tid & 63, kq = tid >> 6;
    float acc[4][4] = {};
    for (int k0 = 0; k0 < 2*H_; k0 += 32) {
        const float* xs = g_cat + ((size_t)(r0 + li))*(2*H_) + k0 + kq*8;
        const float* ws = Wlin + li*(2*H_) + k0 + kq*8;
#pragma unroll
        for (int u = 0; u < 8; ++u) { Xs[kq*8+u][li] = xs[u]; Ws[kq*8+u][li] = ws[u]; }
        __syncthreads();
#pragma unroll
        for (int kk = 0; kk < 32; ++kk) {
            float a[4], w[4];
            *(float4*)a = *(const float4*)&Xs[kk][ty*4];
            *(float4*)w = *(const float4*)&Ws[kk][tx*4];
#pragma unroll
            for (int ii = 0; ii < 4; ++ii)
#pragma unroll
                for (int jj = 0; jj < 4; ++jj) acc[ii][jj] += a[ii]*w[jj];
        }
        __syncthreads();
    }
#pragma unroll
    for (int ii = 0; ii < 4; ++ii) {
        int r = r0 + ty*4 + ii;
#pragma unroll
        for (int jj = 0; jj < 4; ++jj) {
            int l = tx*4 + jj;
            out[r*L_ + l] = acc[ii][jj] + blin[l];
        }
    }
}

// ---------------- launch ----------------
extern "C" void kernel_launch(void* const* d_in, const int* in_sizes, int n_in,
                              void* d_out, int out_size) {
    const int*   chars   = (const int*)  d_in[0];
    const int*   lengths = (const int*)  d_in[1];
    const float* forget  = (const float*)d_in[2];
    const float* W_ih_f  = (const float*)d_in[3];
    const float* W_hh_f  = (const float*)d_in[4];
    const float* b_ih_f  = (const float*)d_in[5];
    const float* b_hh_f  = (const float*)d_in[6];
    const float* W_ih_b  = (const float*)d_in[7];
    const float* W_hh_b  = (const float*)d_in[8];
    const float* b_ih_b  = (const float*)d_in[9];
    const float* b_hh_b  = (const float*)d_in[10];
    const float* W_lin   = (const float*)d_in[11];
    const float* b_lin   = (const float*)d_in[12];
    float* out = (float*)d_out;

    static bool attr_set = false;
    if (!attr_set){
        cudaFuncSetAttribute(k_step, cudaFuncAttributeMaxDynamicSharedMemorySize, STEP_SMEM);
        attr_set = true;
    }

    k_zero<<<1024, 256>>>();
    k_prep<<<(2*G3_*H_ + 255)/256, 256>>>(W_hh_f, W_hh_b);
    k_fofe<<<B_*S_, V_>>>(chars, forget);
    k_xw  <<<dim3(G3_/64, (S_*B_)/64, 2), 256>>>(W_ih_f, W_ih_b, b_ih_f, b_ih_b, lengths);
    for (int t = 0; t < S_; ++t)
        k_step<<<dim3(32, 2, 2), 256, STEP_SMEM>>>(lengths, b_hh_f, b_hh_b, t);
    k_cat<<<dim3(S_, B_), 256>>>(lengths);
    k_lin<<<(S_*B_)/64, 256>>>(W_lin, b_lin, out);
}

// round 7
// speedup vs baseline: 3.2496x; 1.5413x over previous
#include <cuda_runtime.h>
#include <cuda_bf16.h>
#include <math.h>
#include <stdint.h>

#define B_  128
#define S_  128
#define W_  16
#define V_  128
#define H_  512
#define G3_ 1536
#define L_  64

// k_step smem layout
#define WPSZ  49920                    // 48 rows x 1040B per precision
#define OFF_W 0                        // 2 prec -> 99840
#define ASZ   17408                    // 64 rows x 272B
#define OFF_A 99840                    // [buf][prec] x 17408 -> 69632
#define OFF_C 169472                   // 48 x 68 fp32 = 13056
#define STEP_SMEM 182528

// k_xws smem layout (floats, padded stride 129)
#define XWS_WS 0                       // 128 x 129 fp32 = 66048 B
#define XWS_OS 66048                   // 128 x 129 fp32 = 66048 B
#define XWS_CS 132096                  // 128 x 16 int   = 8192 B
#define XWS_FS 140288                  // 128 x 16 fp32  = 8192 B
#define XWS_SMEM 148480

// ---------------- scratch (device globals; no allocation) ----------------
__device__ float g_wt [B_*S_*W_];                     // FOFE weights per (b,s,w)
__device__ float g_xw [(size_t)2*S_*G3_*B_];          // [dir][t][g][b] incl b_ih
__device__ __nv_bfloat16 g_hbf[2][2][2][B_][H_];      // [parity][dir][prec][b][k]
__device__ __nv_bfloat16 g_wp [2][2][G3_][H_];        // [prec][dir][perm row][k]
__device__ float g_gru[(size_t)2*S_*B_*H_];           // [dir][t][b][u]
__device__ float g_cat[(size_t)B_*S_*2*H_];
__device__ int   g_bar;

// ---------------- helpers ----------------
__device__ __forceinline__ uint32_t s2u(const void* p){
    uint32_t a;
    asm("{ .reg .u64 t; cvta.to.shared.u64 t, %1; cvt.u32.u64 %0, t; }" : "=r"(a) : "l"(p));
    return a;
}
__device__ __forceinline__ void ldsm4(uint32_t* r, uint32_t a){
    asm volatile("ldmatrix.sync.aligned.m8n8.x4.shared.b16 {%0,%1,%2,%3}, [%4];"
        : "=r"(r[0]), "=r"(r[1]), "=r"(r[2]), "=r"(r[3]) : "r"(a));
}
__device__ __forceinline__ void ldsm2(uint32_t* r, uint32_t a){
    asm volatile("ldmatrix.sync.aligned.m8n8.x2.shared.b16 {%0,%1}, [%2];"
        : "=r"(r[0]), "=r"(r[1]) : "r"(a));
}
__device__ __forceinline__ void mma16816(float* c, const uint32_t* a, const uint32_t* b){
    asm volatile("mma.sync.aligned.m16n8k16.row.col.f32.bf16.bf16.f32 "
        "{%0,%1,%2,%3}, {%4,%5,%6,%7}, {%8,%9}, {%0,%1,%2,%3};"
        : "+f"(c[0]), "+f"(c[1]), "+f"(c[2]), "+f"(c[3])
        : "r"(a[0]), "r"(a[1]), "r"(a[2]), "r"(a[3]), "r"(b[0]), "r"(b[1]));
}
__device__ __forceinline__ void cpa16(uint32_t dst, const void* src){
    asm volatile("cp.async.cg.shared.global [%0], [%1], 16;" :: "r"(dst), "l"(src));
}

// ---------------- init (re-run every replay) ----------------
__global__ void k_zero(){
    int i = blockIdx.x * 256 + threadIdx.x;
    if (i < 4*B_*H_) ((uint32_t*)g_hbf)[i] = 0u;   // all parities/dirs/precs
    if (i == 0) g_bar = 0;
}

// ---------------- permute + split W_hh into bf16 hi/lo --------------------
__global__ void k_prep(const float* __restrict__ Wf, const float* __restrict__ Wb){
    int e = blockIdx.x * 256 + threadIdx.x;
    if (e >= 2*G3_*H_) return;
    int dir = e / (G3_*H_);
    int rem = e - dir*(G3_*H_);
    int ro  = rem / H_;
    int k   = rem % H_;
    int u = ro / 3, g = ro % 3;
    float w = (dir ? Wb : Wf)[(g*H_ + u)*H_ + k];
    __nv_bfloat16 hi = __float2bfloat16(w);
    __nv_bfloat16 lo = __float2bfloat16(w - __bfloat162float(hi));
    g_wp[0][dir][ro][k] = hi;
    g_wp[1][dir][ro][k] = lo;
}

// ---------------- FOFE weights per (b,s,w) ----------------
__global__ void k_wts(const int* __restrict__ chars, const float* __restrict__ forget_p){
    int bs = blockIdx.x * 256 + threadIdx.x;
    if (bs >= B_*S_) return;
    const int* cp = chars + bs*W_;
    float f = forget_p[0];
    int c[W_];
#pragma unroll
    for (int w = 0; w < W_; ++w) c[w] = cp[w];
    int cnt = 0;
    float wt[W_];
#pragma unroll
    for (int w = W_-1; w >= 0; --w){
        wt[w] = (c[w] != 0) ? powf(f, (float)cnt) : 0.f;
        cnt += (c[w] != 0);
    }
#pragma unroll
    for (int w = 0; w < W_; ++w) g_wt[bs*W_ + w] = wt[w];
}

// ---------------- sparse xw: xw[dir][t][g][b] = b_ih[g] + sum_w wt*W[g][c_w]
__global__ void __launch_bounds__(256)
k_xws(const int* __restrict__ chars, const int* __restrict__ lengths,
      const float* __restrict__ Wf, const float* __restrict__ Wb,
      const float* __restrict__ bf, const float* __restrict__ bb){
    extern __shared__ char sm[];
    float* Ws = (float*)(sm + XWS_WS);   // [v][129]
    float* Os = (float*)(sm + XWS_OS);   // [g][129]
    int*   Cs = (int*)  (sm + XWS_CS);   // [b][16] (prescaled by 129)
    float* Fs = (float*)(sm + XWS_FS);   // [b][16]
    const int tid = threadIdx.x;
    const int gt = blockIdx.x, t = blockIdx.y, dir = blockIdx.z;
    const int g0 = gt * 128;
    const float* Wih = dir ? Wb : Wf;
    const float* bih = dir ? bb : bf;

    for (int i = tid; i < 16384; i += 256){
        int v = i & 127, gl = i >> 7;
        Ws[v*129 + gl] = Wih[(g0 + gl)*V_ + v];
    }
    for (int i = tid; i < 2048; i += 256){
        int b = i >> 4, w = i & 15;
        int s = t;
        if (dir){ s = lengths[b] - 1 - t; if (s < 0) s = 0; }
        int bs = b*S_ + s;
        Cs[b*16 + w] = chars[bs*W_ + w] * 129;
        Fs[b*16 + w] = g_wt[bs*W_ + w];
    }
    __syncthreads();

    const int g = tid & 127, rh = tid >> 7;
    const float bias = bih[g0 + g];
    for (int rr = 0; rr < 64; ++rr){
        const int row = rh*64 + rr;
        const int*   cr = Cs + row*16;
        const float* fr = Fs + row*16;
        float acc = bias;
#pragma unroll
        for (int w = 0; w < W_; ++w) acc = fmaf(fr[w], Ws[cr[w] + g], acc);
        Os[g*129 + row] = acc;
    }
    __syncthreads();

    float* dst = g_xw + ((size_t)(dir*S_ + t)*G3_ + g0)*B_;
    for (int i = tid; i < 16384; i += 256){
        int gl = i >> 7, b = i & 127;
        dst[gl*B_ + b] = Os[gl*129 + b];
    }
}

// ---------------- persistent recurrent kernel (HMMA + gates) ---------------
__global__ void __launch_bounds__(256)
k_step_pers(const int* __restrict__ lengths, const float* __restrict__ bhf,
            const float* __restrict__ bhb){
    extern __shared__ char sm[];
    const uint32_t sb = s2u(sm);
    const int tid  = threadIdx.x;
    const int lane = tid & 31;
    const int wid  = tid >> 5;
    const int wm = wid & 3, wn = wid >> 2;
    const int cu = blockIdx.x, bh = blockIdx.y, dir = blockIdx.z;

    // resident W slice: 2 prec x 48 rows x 512 k, row stride 1040B (once)
    for (int i = tid; i < 6144; i += 256){
        int p = i / 3072, j = i % 3072;
        int row = j >> 6, seg = j & 63;
        cpa16(sb + OFF_W + p*WPSZ + row*1040 + seg*16,
              &g_wp[p][dir][cu*48 + row][seg*8]);
    }
    asm volatile("cp.async.commit_group;");

    // hoisted epilogue constants
    const int bloc = tid & 63, ub = tid >> 6;
    const int bg = bh*64 + bloc;
    const int mylen = lengths[bg];
    const int ubase = cu*16 + ub*4;
    const float* bhv = dir ? bhb : bhf;
    float bR[4], bZ[4], bN[4];
#pragma unroll
    for (int i = 0; i < 4; ++i){
        int u = ubase + i;
        bR[i] = bhv[u]; bZ[i] = bhv[H_ + u]; bN[i] = bhv[2*H_ + u];
    }
    float hreg[4] = {0.f, 0.f, 0.f, 0.f};

    const int ln = lane & 15;
    const uint32_t aoff = (uint32_t)(wm*16 + (lane & 15))*272 + (uint32_t)(lane >> 4)*16;
    const uint32_t boffr = (uint32_t)(wn*24 + (ln & 7))*1040 + (uint32_t)(ln >> 3)*16;
    float* Cs = (float*)(sm + OFF_C);

    asm volatile("cp.async.wait_group 0;");
    __syncthreads();

    for (int t = 0; t < S_; ++t){
        const int par = t & 1;

        // prefetch xw (coalesced along b in [dir][t][g][b] layout)
        float xr[4], xz[4], xn[4];
        {
            const float* xwb = g_xw + ((size_t)(dir*S_ + t))*G3_*B_;
#pragma unroll
            for (int i = 0; i < 4; ++i){
                int u = ubase + i;
                xr[i] = xwb[(size_t)u*B_ + bg];
                xz[i] = xwb[(size_t)(H_ + u)*B_ + bg];
                xn[i] = xwb[(size_t)(2*H_ + u)*B_ + bg];
            }
        }

        // h chunks 0,1
#pragma unroll
        for (int c = 0; c < 2; ++c){
#pragma unroll
            for (int p = 0; p < 2; ++p)
#pragma unroll
                for (int j = 0; j < 4; ++j){
                    int i = tid + j*256;
                    int row = i >> 4, seg = i & 15;
                    cpa16(sb + OFF_A + (c*2 + p)*ASZ + row*272 + seg*16,
                          &g_hbf[par][dir][p][bh*64 + row][c*128 + seg*8]);
                }
            asm volatile("cp.async.commit_group;");
        }

        float acc[3][4] = {};
        for (int c = 0; c < 4; ++c){
            if (c < 3) asm volatile("cp.async.wait_group 1;");
            else       asm volatile("cp.async.wait_group 0;");
            __syncthreads();
            const int buf = c & 1;
            const uint32_t Ah = sb + OFF_A + (buf*2)*ASZ + aoff;
            const uint32_t Al = Ah + ASZ;
            const uint32_t Bb = sb + OFF_W + boffr + (uint32_t)c*256;
#pragma unroll
            for (int ks = 0; ks < 8; ++ks){
                uint32_t aH[4], aL[4];
                ldsm4(aH, Ah + ks*32);
                ldsm4(aL, Al + ks*32);
#pragma unroll
                for (int nt = 0; nt < 3; ++nt){
                    uint32_t bHr[2], bLr[2];
                    uint32_t ba = Bb + (uint32_t)nt*8*1040 + (uint32_t)ks*32;
                    ldsm2(bHr, ba);
                    ldsm2(bLr, ba + WPSZ);
                    mma16816(acc[nt], aH, bHr);
                    mma16816(acc[nt], aL, bHr);
                    mma16816(acc[nt], aH, bLr);
                }
            }
            __syncthreads();
            if (c < 2){
#pragma unroll
                for (int p = 0; p < 2; ++p)
#pragma unroll
                    for (int j = 0; j < 4; ++j){
                        int i = tid + j*256;
                        int row = i >> 4, seg = i & 15;
                        cpa16(sb + OFF_A + (buf*2 + p)*ASZ + row*272 + seg*16,
                              &g_hbf[par][dir][p][bh*64 + row][(c+2)*128 + seg*8]);
                    }
                asm volatile("cp.async.commit_group;");
            }
        }

        // stage C: Cs[n 48][m 64], stride 68
        {
            const int trow = lane >> 2, tcol = (lane & 3)*2;
#pragma unroll
            for (int nt = 0; nt < 3; ++nt){
                int n = wn*24 + nt*8 + tcol;
                int m = wm*16 + trow;
                Cs[n*68 + m]          = acc[nt][0];
                Cs[(n+1)*68 + m]      = acc[nt][1];
                Cs[n*68 + m + 8]      = acc[nt][2];
                Cs[(n+1)*68 + m + 8]  = acc[nt][3];
            }
        }
        __syncthreads();

        // gates + state update
        {
            const bool msk = (t < mylen);
            const int par2 = par ^ 1;
            float gv[4];
#pragma unroll
            for (int i = 0; i < 4; ++i){
                const int ul = ub*4 + i;
                float pr = Cs[(ul*3+0)*68 + bloc] + bR[i] + xr[i];
                float pz = Cs[(ul*3+1)*68 + bloc] + bZ[i] + xz[i];
                float pn = Cs[(ul*3+2)*68 + bloc] + bN[i];
                float r = 1.f/(1.f + expf(-pr));
                float z = 1.f/(1.f + expf(-pz));
                float n = tanhf(xn[i] + r*pn);
                float hnew = (1.f - z)*n + z*hreg[i];
                gv[i] = msk ? hnew : 0.f;
                if (msk) hreg[i] = hnew;
            }
            *(float4*)&g_gru[(((size_t)dir*S_ + t)*B_ + bg)*H_ + ubase] = *(float4*)gv;
            __nv_bfloat16 hi[4], lo[4];
#pragma unroll
            for (int i = 0; i < 4; ++i){
                hi[i] = __float2bfloat16(hreg[i]);
                lo[i] = __float2bfloat16(hreg[i] - __bfloat162float(hi[i]));
            }
            *(uint2*)&g_hbf[par2][dir][0][bg][ubase] = *(uint2*)hi;
            *(uint2*)&g_hbf[par2][dir][1][bg][ubase] = *(uint2*)lo;
        }

        // grid barrier (single wave: 128 CTAs, 1/SM)
        __threadfence();
        __syncthreads();
        if (tid == 0){
            atomicAdd(&g_bar, 1);
            const int target = 128*(t+1);
            int v;
            do {
                asm volatile("ld.global.acquire.gpu.b32 %0, [%1];" : "=r"(v) : "l"(&g_bar));
            } while (v < target);
        }
        __syncthreads();
    }
}

// ---------------- gather/concat rows for final linear ---------------------
__global__ void k_cat(const int* __restrict__ lengths) {
    const int s = blockIdx.x, b = blockIdx.y;
    const int len = lengths[b];
    float* dst = g_cat + ((size_t)b*S_ + s)*(2*H_);
    for (int j = threadIdx.x; j < 2*H_; j += blockDim.x) {
        float v;
        if (j < H_)            v = g_gru[((size_t)s*B_ + b)*H_ + j];
        else if (s < len)      v = g_gru[((size_t)(S_ + (len-1-s))*B_ + b)*H_ + (j - H_)];
        else                   v = 0.f;
        dst[j] = v;
    }
}

// ---------------- final linear ----------------
__global__ void k_lin(const float* __restrict__ Wlin, const float* __restrict__ blin,
                      float* __restrict__ out) {
    __shared__ float Xs[32][64];
    __shared__ float Ws[32][64];
    const int tid = threadIdx.x;
    const int r0 = blockIdx.x * 64;
    const int ty = tid >> 4, tx = tid & 15;
    const int li = tid & 63, kq = tid >> 6;
    float acc[4][4] = {};
    for (int k0 = 0; k0 < 2*H_; k0 += 32) {
        const float* xs = g_cat + ((size_t)(r0 + li))*(2*H_) + k0 + kq*8;
        const float* ws = Wlin + li*(2*H_) + k0 + kq*8;
#pragma unroll
        for (int u = 0; u < 8; ++u) { Xs[kq*8+u][li] = xs[u]; Ws[kq*8+u][li] = ws[u]; }
        __syncthreads();
#pragma unroll
        for (int kk = 0; kk < 32; ++kk) {
            float a[4], w[4];
            *(float4*)a = *(const float4*)&Xs[kk][ty*4];
            *(float4*)w = *(const float4*)&Ws[kk][tx*4];
#pragma unroll
            for (int ii = 0; ii < 4; ++ii)
#pragma unroll
                for (int jj = 0; jj < 4; ++jj) acc[ii][jj] += a[ii]*w[jj];
        }
        __syncthreads();
    }
#pragma unroll
    for (int ii = 0; ii < 4; ++ii) {
        int r = r0 + ty*4 + ii;
#pragma unroll
        for (int jj = 0; jj < 4; ++jj) {
            int l = tx*4 + jj;
            out[r*L_ + l] = acc[ii][jj] + blin[l];
        }
    }
}

// ---------------- launch ----------------
extern "C" void kernel_launch(void* const* d_in, const int* in_sizes, int n_in,
                              void* d_out, int out_size) {
    const int*   chars   = (const int*)  d_in[0];
    const int*   lengths = (const int*)  d_in[1];
    const float* forget  = (const float*)d_in[2];
    const float* W_ih_f  = (const float*)d_in[3];
    const float* W_hh_f  = (const float*)d_in[4];
    const float* b_ih_f  = (const float*)d_in[5];
    const float* b_hh_f  = (const float*)d_in[6];
    const float* W_ih_b  = (const float*)d_in[7];
    const float* W_hh_b  = (const float*)d_in[8];
    const float* b_ih_b  = (const float*)d_in[9];
    const float* b_hh_b  = (const float*)d_in[10];
    const float* W_lin   = (const float*)d_in[11];
    const float* b_lin   = (const float*)d_in[12];
    float* out = (float*)d_out;

    cudaFuncSetAttribute(k_step_pers, cudaFuncAttributeMaxDynamicSharedMemorySize, STEP_SMEM);
    cudaFuncSetAttribute(k_xws, cudaFuncAttributeMaxDynamicSharedMemorySize, XWS_SMEM);

    k_zero<<<1024, 256>>>();
    k_prep<<<(2*G3_*H_ + 255)/256, 256>>>(W_hh_f, W_hh_b);
    k_wts <<<(B_*S_ + 255)/256, 256>>>(chars, forget);
    k_xws <<<dim3(G3_/128, S_, 2), 256, XWS_SMEM>>>(chars, lengths, W_ih_f, W_ih_b, b_ih_f, b_ih_b);
    k_step_pers<<<dim3(32, 2, 2), 256, STEP_SMEM>>>(lengths, b_hh_f, b_hh_b);
    k_cat<<<dim3(S_, B_), 256>>>(lengths);
    k_lin<<<(S_*B_)/64, 256>>>(W_lin, b_lin, out);
}

// round 10
// speedup vs baseline: 3.8499x; 1.1847x over previous
#include <cuda_runtime.h>
#include <cuda_bf16.h>
#include <math.h>
#include <stdint.h>

#define B_  128
#define S_  128
#define W_  16
#define V_  128
#define H_  512
#define G3_ 1536
#define L_  64

// k_step smem layout
#define WPSZ  49920                    // 48 rows x 1040B per precision
#define OFF_W 0                        // 2 prec -> 99840
#define ASZ   17408                    // 64 rows x 272B
#define OFF_A 99840                    // [buf][prec] x 17408 -> 69632
#define OFF_C 169472                   // 48 x 68 fp32 = 13056
#define STEP_SMEM 182528

// k_xws smem layout (g-tile 64)
#define XT_G  64
#define XS_WS 0                        // 128 v x 65 fp32 = 33280 B
#define XS_OS 33280                    // 64 g x 129 fp32 = 33024 B
#define XS_CS 66304                    // 128 b x 16 int  = 8192 B
#define XS_FS 74496                    // 128 b x 16 fp32 = 8192 B
#define XS_SMEM 82688

// ---------------- scratch (device globals; no allocation) ----------------
__device__ float g_wt [B_*S_*W_];                     // FOFE weights per (b,s,w)
__device__ float g_xw [(size_t)2*S_*G3_*B_];          // [dir][t][g][b] incl b_ih
__device__ __nv_bfloat16 g_hbf[2][2][2][B_][H_];      // [parity][dir][prec][b][k]
__device__ __nv_bfloat16 g_wp [2][2][G3_][H_];        // [prec][dir][perm row][k]
__device__ float g_gru[(size_t)2*S_*B_*H_];           // [dir][t][b][u]
__device__ int   g_bar;

// ---------------- helpers ----------------
__device__ __forceinline__ uint32_t s2u(const void* p){
    uint32_t a;
    asm("{ .reg .u64 t; cvta.to.shared.u64 t, %1; cvt.u32.u64 %0, t; }" : "=r"(a) : "l"(p));
    return a;
}
__device__ __forceinline__ void ldsm4(uint32_t* r, uint32_t a){
    asm volatile("ldmatrix.sync.aligned.m8n8.x4.shared.b16 {%0,%1,%2,%3}, [%4];"
        : "=r"(r[0]), "=r"(r[1]), "=r"(r[2]), "=r"(r[3]) : "r"(a));
}
__device__ __forceinline__ void ldsm2(uint32_t* r, uint32_t a){
    asm volatile("ldmatrix.sync.aligned.m8n8.x2.shared.b16 {%0,%1}, [%2];"
        : "=r"(r[0]), "=r"(r[1]) : "r"(a));
}
__device__ __forceinline__ void mma16816(float* c, const uint32_t* a, const uint32_t* b){
    asm volatile("mma.sync.aligned.m16n8k16.row.col.f32.bf16.bf16.f32 "
        "{%0,%1,%2,%3}, {%4,%5,%6,%7}, {%8,%9}, {%0,%1,%2,%3};"
        : "+f"(c[0]), "+f"(c[1]), "+f"(c[2]), "+f"(c[3])
        : "r"(a[0]), "r"(a[1]), "r"(a[2]), "r"(a[3]), "r"(b[0]), "r"(b[1]));
}
__device__ __forceinline__ void cpa16(uint32_t dst, const void* src){
    asm volatile("cp.async.cg.shared.global [%0], [%1], 16;" :: "r"(dst), "l"(src));
}

// ---------------- init (re-run every replay) ----------------
__global__ void k_zero(){
    int i = blockIdx.x * 256 + threadIdx.x;
    if (i < 4*B_*H_) ((uint32_t*)g_hbf)[i] = 0u;
    if (i == 0) g_bar = 0;
}

// ---------------- permute + split W_hh into bf16 hi/lo --------------------
__global__ void k_prep(const float* __restrict__ Wf, const float* __restrict__ Wb){
    int e = blockIdx.x * 256 + threadIdx.x;
    if (e >= 2*G3_*H_) return;
    int dir = e / (G3_*H_);
    int rem = e - dir*(G3_*H_);
    int ro  = rem / H_;
    int k   = rem % H_;
    int u = ro / 3, g = ro % 3;
    float w = (dir ? Wb : Wf)[(g*H_ + u)*H_ + k];
    __nv_bfloat16 hi = __float2bfloat16(w);
    __nv_bfloat16 lo = __float2bfloat16(w - __bfloat162float(hi));
    g_wp[0][dir][ro][k] = hi;
    g_wp[1][dir][ro][k] = lo;
}

// ---------------- FOFE weights per (b,s,w) ----------------
__global__ void k_wts(const int* __restrict__ chars, const float* __restrict__ forget_p){
    int bs = blockIdx.x * 256 + threadIdx.x;
    if (bs >= B_*S_) return;
    const int* cp = chars + bs*W_;
    float f = forget_p[0];
    int c[W_];
#pragma unroll
    for (int w = 0; w < W_; ++w) c[w] = cp[w];
    int cnt = 0;
    float wt[W_];
#pragma unroll
    for (int w = W_-1; w >= 0; --w){
        wt[w] = (c[w] != 0) ? powf(f, (float)cnt) : 0.f;
        cnt += (c[w] != 0);
    }
#pragma unroll
    for (int w = 0; w < W_; ++w) g_wt[bs*W_ + w] = wt[w];
}

// ---------------- sparse xw: xw[dir][t][g][b] = b_ih[g] + sum_w wt*W[g][c_w]
__global__ void __launch_bounds__(256)
k_xws(const int* __restrict__ chars, const int* __restrict__ lengths,
      const float* __restrict__ Wf, const float* __restrict__ Wb,
      const float* __restrict__ bf, const float* __restrict__ bb){
    extern __shared__ char sm[];
    float* Wsm = (float*)(sm + XS_WS);   // [v][65]
    float* Os  = (float*)(sm + XS_OS);   // [g][129]
    int*   Cs  = (int*)  (sm + XS_CS);   // [b][16] (prescaled by 65)
    float* Fs  = (float*)(sm + XS_FS);   // [b][16]
    const int tid = threadIdx.x;
    const int gt = blockIdx.x, t = blockIdx.y, dir = blockIdx.z;
    const int g0 = gt * XT_G;
    const float* Wih = dir ? Wb : Wf;
    const float* bih = dir ? bb : bf;

    // W tile transposed [v][g], stride 65
    for (int i = tid; i < XT_G*V_; i += 256){
        int v = i & 127, gl = i >> 7;
        Wsm[v*65 + gl] = Wih[(g0 + gl)*V_ + v];
    }
    for (int i = tid; i < B_*W_; i += 256){
        int b = i >> 4, w = i & 15;
        int s = t;
        if (dir){ s = lengths[b] - 1 - t; if (s < 0) s = 0; }
        int bs = b*S_ + s;
        Cs[i] = chars[bs*W_ + w] * 65;
        Fs[i] = g_wt[bs*W_ + w];
    }
    __syncthreads();

    const int g = tid & 63, q = tid >> 6;
    const float bias = bih[g0 + g];
#pragma unroll
    for (int rr = 0; rr < 32; rr += 4){
        const int row = q*32 + rr;                 // 4 consecutive rows: row..row+3
        const int*   cr = Cs + row*16;
        const float* fr = Fs + row*16;
        float a0 = bias, a1 = bias, a2 = bias, a3 = bias;
#pragma unroll
        for (int w0 = 0; w0 < 16; w0 += 4){
            int4   c0 = *(const int4*)  (cr + w0);
            int4   c1 = *(const int4*)  (cr + 16 + w0);
            int4   c2 = *(const int4*)  (cr + 32 + w0);
            int4   c3 = *(const int4*)  (cr + 48 + w0);
            float4 f0 = *(const float4*)(fr + w0);
            float4 f1 = *(const float4*)(fr + 16 + w0);
            float4 f2 = *(const float4*)(fr + 32 + w0);
            float4 f3 = *(const float4*)(fr + 48 + w0);
            a0 = fmaf(f0.x, Wsm[c0.x + g], a0);
            a1 = fmaf(f1.x, Wsm[c1.x + g], a1);
            a2 = fmaf(f2.x, Wsm[c2.x + g], a2);
            a3 = fmaf(f3.x, Wsm[c3.x + g], a3);
            a0 = fmaf(f0.y, Wsm[c0.y + g], a0);
            a1 = fmaf(f1.y, Wsm[c1.y + g], a1);
            a2 = fmaf(f2.y, Wsm[c2.y + g], a2);
            a3 = fmaf(f3.y, Wsm[c3.y + g], a3);
            a0 = fmaf(f0.z, Wsm[c0.z + g], a0);
            a1 = fmaf(f1.z, Wsm[c1.z + g], a1);
            a2 = fmaf(f2.z, Wsm[c2.z + g], a2);
            a3 = fmaf(f3.z, Wsm[c3.z + g], a3);
            a0 = fmaf(f0.w, Wsm[c0.w + g], a0);
            a1 = fmaf(f1.w, Wsm[c1.w + g], a1);
            a2 = fmaf(f2.w, Wsm[c2.w + g], a2);
            a3 = fmaf(f3.w, Wsm[c3.w + g], a3);
        }
        // FIX: stores match computed rows row..row+3 (R9 bug: +16/+32/+48 OOB)
        Os[g*129 + row]     = a0;
        Os[g*129 + row + 1] = a1;
        Os[g*129 + row + 2] = a2;
        Os[g*129 + row + 3] = a3;
    }
    __syncthreads();

    float* dst = g_xw + ((size_t)(dir*S_ + t)*G3_ + g0)*B_;
    for (int i = tid; i < XT_G*B_; i += 256){
        int gl = i >> 7, b = i & 127;
        dst[gl*B_ + b] = Os[gl*129 + b];
    }
}

// ---------------- persistent recurrent kernel (HMMA + gates) ---------------
__global__ void __launch_bounds__(256)
k_step_pers(const int* __restrict__ lengths, const float* __restrict__ bhf,
            const float* __restrict__ bhb){
    extern __shared__ char sm[];
    const uint32_t sb = s2u(sm);
    const int tid  = threadIdx.x;
    const int lane = tid & 31;
    const int wid  = tid >> 5;
    const int wm = wid & 3, wn = wid >> 2;
    const int cu = blockIdx.x, bh = blockIdx.y, dir = blockIdx.z;

    for (int i = tid; i < 6144; i += 256){
        int p = i / 3072, j = i % 3072;
        int row = j >> 6, seg = j & 63;
        cpa16(sb + OFF_W + p*WPSZ + row*1040 + seg*16,
              &g_wp[p][dir][cu*48 + row][seg*8]);
    }
    asm volatile("cp.async.commit_group;");

    const int bloc = tid & 63, ub = tid >> 6;
    const int bg = bh*64 + bloc;
    const int mylen = lengths[bg];
    const int ubase = cu*16 + ub*4;
    const float* bhv = dir ? bhb : bhf;
    float bR[4], bZ[4], bN[4];
#pragma unroll
    for (int i = 0; i < 4; ++i){
        int u = ubase + i;
        bR[i] = bhv[u]; bZ[i] = bhv[H_ + u]; bN[i] = bhv[2*H_ + u];
    }
    float hreg[4] = {0.f, 0.f, 0.f, 0.f};

    const int ln = lane & 15;
    const uint32_t aoff = (uint32_t)(wm*16 + (lane & 15))*272 + (uint32_t)(lane >> 4)*16;
    const uint32_t boffr = (uint32_t)(wn*24 + (ln & 7))*1040 + (uint32_t)(ln >> 3)*16;
    float* Cs = (float*)(sm + OFF_C);

    asm volatile("cp.async.wait_group 0;");
    __syncthreads();

    for (int t = 0; t < S_; ++t){
        const int par = t & 1;

        float xr[4], xz[4], xn[4];
        {
            const float* xwb = g_xw + ((size_t)(dir*S_ + t))*G3_*B_;
#pragma unroll
            for (int i = 0; i < 4; ++i){
                int u = ubase + i;
                xr[i] = xwb[(size_t)u*B_ + bg];
                xz[i] = xwb[(size_t)(H_ + u)*B_ + bg];
                xn[i] = xwb[(size_t)(2*H_ + u)*B_ + bg];
            }
        }

#pragma unroll
        for (int c = 0; c < 2; ++c){
#pragma unroll
            for (int p = 0; p < 2; ++p)
#pragma unroll
                for (int j = 0; j < 4; ++j){
                    int i = tid + j*256;
                    int row = i >> 4, seg = i & 15;
                    cpa16(sb + OFF_A + (c*2 + p)*ASZ + row*272 + seg*16,
                          &g_hbf[par][dir][p][bh*64 + row][c*128 + seg*8]);
                }
            asm volatile("cp.async.commit_group;");
        }

        float acc[3][4] = {};
        for (int c = 0; c < 4; ++c){
            if (c < 3) asm volatile("cp.async.wait_group 1;");
            else       asm volatile("cp.async.wait_group 0;");
            __syncthreads();
            const int buf = c & 1;
            const uint32_t Ah = sb + OFF_A + (buf*2)*ASZ + aoff;
            const uint32_t Al = Ah + ASZ;
            const uint32_t Bb = sb + OFF_W + boffr + (uint32_t)c*256;
#pragma unroll
            for (int ks = 0; ks < 8; ++ks){
                uint32_t aH[4], aL[4];
                ldsm4(aH, Ah + ks*32);
                ldsm4(aL, Al + ks*32);
#pragma unroll
                for (int nt = 0; nt < 3; ++nt){
                    uint32_t bHr[2], bLr[2];
                    uint32_t ba = Bb + (uint32_t)nt*8*1040 + (uint32_t)ks*32;
                    ldsm2(bHr, ba);
                    ldsm2(bLr, ba + WPSZ);
                    mma16816(acc[nt], aH, bHr);
                    mma16816(acc[nt], aL, bHr);
                    mma16816(acc[nt], aH, bLr);
                }
            }
            __syncthreads();
            if (c < 2){
#pragma unroll
                for (int p = 0; p < 2; ++p)
#pragma unroll
                    for (int j = 0; j < 4; ++j){
                        int i = tid + j*256;
                        int row = i >> 4, seg = i & 15;
                        cpa16(sb + OFF_A + (buf*2 + p)*ASZ + row*272 + seg*16,
                              &g_hbf[par][dir][p][bh*64 + row][(c+2)*128 + seg*8]);
                    }
                asm volatile("cp.async.commit_group;");
            }
        }

        {
            const int trow = lane >> 2, tcol = (lane & 3)*2;
#pragma unroll
            for (int nt = 0; nt < 3; ++nt){
                int n = wn*24 + nt*8 + tcol;
                int m = wm*16 + trow;
                Cs[n*68 + m]          = acc[nt][0];
                Cs[(n+1)*68 + m]      = acc[nt][1];
                Cs[n*68 + m + 8]      = acc[nt][2];
                Cs[(n+1)*68 + m + 8]  = acc[nt][3];
            }
        }
        __syncthreads();

        {
            const bool msk = (t < mylen);
            const int par2 = par ^ 1;
            float gv[4];
#pragma unroll
            for (int i = 0; i < 4; ++i){
                const int ul = ub*4 + i;
                float pr = Cs[(ul*3+0)*68 + bloc] + bR[i] + xr[i];
                float pz = Cs[(ul*3+1)*68 + bloc] + bZ[i] + xz[i];
                float pn = Cs[(ul*3+2)*68 + bloc] + bN[i];
                float r = 1.f/(1.f + expf(-pr));
                float z = 1.f/(1.f + expf(-pz));
                float n = tanhf(xn[i] + r*pn);
                float hnew = (1.f - z)*n + z*hreg[i];
                gv[i] = msk ? hnew : 0.f;
                if (msk) hreg[i] = hnew;
            }
            *(float4*)&g_gru[(((size_t)dir*S_ + t)*B_ + bg)*H_ + ubase] = *(float4*)gv;
            __nv_bfloat16 hi[4], lo[4];
#pragma unroll
            for (int i = 0; i < 4; ++i){
                hi[i] = __float2bfloat16(hreg[i]);
                lo[i] = __float2bfloat16(hreg[i] - __bfloat162float(hi[i]));
            }
            *(uint2*)&g_hbf[par2][dir][0][bg][ubase] = *(uint2*)hi;
            *(uint2*)&g_hbf[par2][dir][1][bg][ubase] = *(uint2*)lo;
        }

        __threadfence();
        __syncthreads();
        if (tid == 0){
            atomicAdd(&g_bar, 1);
            const int target = 128*(t+1);
            int v;
            do {
                asm volatile("ld.global.acquire.gpu.b32 %0, [%1];" : "=r"(v) : "l"(&g_bar));
            } while (v < target);
        }
        __syncthreads();
    }
}

// ---------------- final linear (gather fused; k_cat eliminated) -----------
__global__ void k_lin(const float* __restrict__ Wlin, const float* __restrict__ blin,
                      const int* __restrict__ lengths, float* __restrict__ out) {
    __shared__ float Xs[32][64];
    __shared__ float Ws2[32][64];
    __shared__ const float* srcF[64];
    __shared__ const float* srcB[64];
    const int tid = threadIdx.x;
    const int r0 = blockIdx.x * 64;
    if (tid < 64){
        int r = r0 + tid;
        int b = r >> 7, s = r & 127;
        srcF[tid] = g_gru + ((size_t)s*B_ + b)*H_;
        int len = lengths[b];
        srcB[tid] = (s < len) ? g_gru + ((size_t)(S_ + (len-1-s))*B_ + b)*H_ : (const float*)0;
    }
    __syncthreads();
    const int ty = tid >> 4, tx = tid & 15;
    const int li = tid & 63, kq = tid >> 6;
    float acc[4][4] = {};
    for (int k0 = 0; k0 < 2*H_; k0 += 32) {
        const float* ws = Wlin + li*(2*H_) + k0 + kq*8;
        if (k0 < H_){
            const float* xsrc = srcF[li] + k0 + kq*8;
#pragma unroll
            for (int u = 0; u < 8; ++u) { Xs[kq*8+u][li] = xsrc[u]; Ws2[kq*8+u][li] = ws[u]; }
        } else {
            const float* xsrc = srcB[li];
            const int kk0 = k0 - H_ + kq*8;
#pragma unroll
            for (int u = 0; u < 8; ++u) {
                Xs[kq*8+u][li] = xsrc ? xsrc[kk0 + u] : 0.f;
                Ws2[kq*8+u][li] = ws[u];
            }
        }
        __syncthreads();
#pragma unroll
        for (int kk = 0; kk < 32; ++kk) {
            float a[4], w[4];
            *(float4*)a = *(const float4*)&Xs[kk][ty*4];
            *(float4*)w = *(const float4*)&Ws2[kk][tx*4];
#pragma unroll
            for (int ii = 0; ii < 4; ++ii)
#pragma unroll
                for (int jj = 0; jj < 4; ++jj) acc[ii][jj] += a[ii]*w[jj];
        }
        __syncthreads();
    }
#pragma unroll
    for (int ii = 0; ii < 4; ++ii) {
        int r = r0 + ty*4 + ii;
#pragma unroll
        for (int jj = 0; jj < 4; ++jj) {
            int l = tx*4 + jj;
            out[r*L_ + l] = acc[ii][jj] + blin[l];
        }
    }
}

// ---------------- launch ----------------
extern "C" void kernel_launch(void* const* d_in, const int* in_sizes, int n_in,
                              void* d_out, int out_size) {
    const int*   chars   = (const int*)  d_in[0];
    const int*   lengths = (const int*)  d_in[1];
    const float* forget  = (const float*)d_in[2];
    const float* W_ih_f  = (const float*)d_in[3];
    const float* W_hh_f  = (const float*)d_in[4];
    const float* b_ih_f  = (const float*)d_in[5];
    const float* b_hh_f  = (const float*)d_in[6];
    const float* W_ih_b  = (const float*)d_in[7];
    const float* W_hh_b  = (const float*)d_in[8];
    const float* b_ih_b  = (const float*)d_in[9];
    const float* b_hh_b  = (const float*)d_in[10];
    const float* W_lin   = (const float*)d_in[11];
    const float* b_lin   = (const float*)d_in[12];
    float* out = (float*)d_out;

    cudaFuncSetAttribute(k_step_pers, cudaFuncAttributeMaxDynamicSharedMemorySize, STEP_SMEM);
    cudaFuncSetAttribute(k_xws, cudaFuncAttributeMaxDynamicSharedMemorySize, XS_SMEM);

    k_zero<<<1024, 256>>>();
    k_prep<<<(2*G3_*H_ + 255)/256, 256>>>(W_hh_f, W_hh_b);
    k_wts <<<(B_*S_ + 255)/256, 256>>>(chars, forget);
    k_xws <<<dim3(G3_/XT_G, S_, 2), 256, XS_SMEM>>>(chars, lengths, W_ih_f, W_ih_b, b_ih_f, b_ih_b);
    k_step_pers<<<dim3(32, 2, 2), 256, STEP_SMEM>>>(lengths, b_hh_f, b_hh_b);
    k_lin<<<(S_*B_)/64, 256>>>(W_lin, b_lin, lengths, out);
}

// round 13
// speedup vs baseline: 4.5400x; 1.1792x over previous
#include <cuda_runtime.h>
#include <cuda_bf16.h>
#include <math.h>
#include <stdint.h>

#define B_  128
#define S_  128
#define W_  16
#define V_  128
#define H_  512
#define G3_ 1536
#define L_  64

// k_step smem layout
#define WPSZ  49920                    // 48 rows x 1040B per precision
#define OFF_W 0                        // 2 prec -> 99840
#define ASZ   17408                    // 64 rows x 272B
#define OFF_A 99840                    // [buf][prec] x 17408 -> 69632
#define OFF_C 169472                   // 48 x 68 fp32 = 13056
#define STEP_SMEM 182528

// k_xws smem layout (g-tile 64)
#define XT_G  64
#define XS_WS 0
#define XS_OS 33280
#define XS_CS 66304
#define XS_FS 74496
#define XS_SMEM 82688

// k_lin_mma smem layout
#define LASZ  17408                    // 64 rows x 272B
#define LOFF_A 0                       // [buf2][prec2] -> 69632
#define LOFF_B 69632                   // [buf2][prec2] -> 69632
#define LOFF_C 139264                  // 64 x 68 fp32 = 17408
#define LIN_SMEM 156672

// ---------------- scratch (device globals; no allocation) ----------------
__device__ float g_wt [B_*S_*W_];
__device__ float g_xw [(size_t)2*S_*G3_*B_];          // [dir][t][g][b] incl b_ih
__device__ __nv_bfloat16 g_hbf[2][2][2][B_][H_];      // [parity][dir][prec][b][k]
__device__ __nv_bfloat16 g_wp [2][2][G3_][H_];        // [prec][dir][perm row][k]
__device__ __nv_bfloat16 g_gb [2][2][S_][B_][H_];     // [prec][dir][t][b][u] masked out
__device__ __nv_bfloat16 g_wlb[2][L_][2*H_];          // [prec][l][k] W_lin split
__device__ float g_zbuf[64];                          // stays zero (never written)
__device__ int   g_bar4[4];

// ---------------- helpers ----------------
__device__ __forceinline__ uint32_t s2u(const void* p){
    uint32_t a;
    asm("{ .reg .u64 t; cvta.to.shared.u64 t, %1; cvt.u32.u64 %0, t; }" : "=r"(a) : "l"(p));
    return a;
}
__device__ __forceinline__ void ldsm4(uint32_t* r, uint32_t a){
    asm volatile("ldmatrix.sync.aligned.m8n8.x4.shared.b16 {%0,%1,%2,%3}, [%4];"
        : "=r"(r[0]), "=r"(r[1]), "=r"(r[2]), "=r"(r[3]) : "r"(a));
}
__device__ __forceinline__ void ldsm2(uint32_t* r, uint32_t a){
    asm volatile("ldmatrix.sync.aligned.m8n8.x2.shared.b16 {%0,%1}, [%2];"
        : "=r"(r[0]), "=r"(r[1]) : "r"(a));
}
__device__ __forceinline__ void mma16816(float* c, const uint32_t* a, const uint32_t* b){
    asm volatile("mma.sync.aligned.m16n8k16.row.col.f32.bf16.bf16.f32 "
        "{%0,%1,%2,%3}, {%4,%5,%6,%7}, {%8,%9}, {%0,%1,%2,%3};"
        : "+f"(c[0]), "+f"(c[1]), "+f"(c[2]), "+f"(c[3])
        : "r"(a[0]), "r"(a[1]), "r"(a[2]), "r"(a[3]), "r"(b[0]), "r"(b[1]));
}
__device__ __forceinline__ void cpa16(uint32_t dst, const void* src){
    asm volatile("cp.async.cg.shared.global [%0], [%1], 16;" :: "r"(dst), "l"(src));
}
__device__ __forceinline__ float fsig(float x){
    return __fdividef(1.f, 1.f + __expf(-x));
}
__device__ __forceinline__ float ftanh(float x){
    float e = __expf(2.f*fabsf(x));
    return copysignf(1.f - __fdividef(2.f, e + 1.f), x);
}

// ---------------- init (re-run every replay) ----------------
__global__ void k_zero(){
    int i = blockIdx.x * 256 + threadIdx.x;
    if (i < 4*B_*H_) ((uint32_t*)g_hbf)[i] = 0u;
    if (i < 4) g_bar4[i] = 0;
}

// ---------------- permute + split W_hh into bf16 hi/lo --------------------
__global__ void k_prep(const float* __restrict__ Wf, const float* __restrict__ Wb){
    int e = blockIdx.x * 256 + threadIdx.x;
    if (e >= 2*G3_*H_) return;
    int dir = e / (G3_*H_);
    int rem = e - dir*(G3_*H_);
    int ro  = rem / H_;
    int k   = rem % H_;
    int u = ro / 3, g = ro % 3;
    float w = (dir ? Wb : Wf)[(g*H_ + u)*H_ + k];
    __nv_bfloat16 hi = __float2bfloat16(w);
    __nv_bfloat16 lo = __float2bfloat16(w - __bfloat162float(hi));
    g_wp[0][dir][ro][k] = hi;
    g_wp[1][dir][ro][k] = lo;
}

// ---------------- split W_lin into bf16 hi/lo ----------------
__global__ void k_prepL(const float* __restrict__ Wlin){
    int e = blockIdx.x * 256 + threadIdx.x;
    if (e >= L_*2*H_) return;
    float w = Wlin[e];
    __nv_bfloat16 hi = __float2bfloat16(w);
    __nv_bfloat16 lo = __float2bfloat16(w - __bfloat162float(hi));
    ((__nv_bfloat16*)g_wlb)[e] = hi;
    ((__nv_bfloat16*)g_wlb)[L_*2*H_ + e] = lo;
}

// ---------------- FOFE weights per (b,s,w) ----------------
__global__ void k_wts(const int* __restrict__ chars, const float* __restrict__ forget_p){
    int bs = blockIdx.x * 256 + threadIdx.x;
    if (bs >= B_*S_) return;
    const int* cp = chars + bs*W_;
    float f = forget_p[0];
    int c[W_];
#pragma unroll
    for (int w = 0; w < W_; ++w) c[w] = cp[w];
    int cnt = 0;
    float wt[W_];
#pragma unroll
    for (int w = W_-1; w >= 0; --w){
        wt[w] = (c[w] != 0) ? powf(f, (float)cnt) : 0.f;
        cnt += (c[w] != 0);
    }
#pragma unroll
    for (int w = 0; w < W_; ++w) g_wt[bs*W_ + w] = wt[w];
}

// ---------------- sparse xw ----------------
__global__ void __launch_bounds__(256)
k_xws(const int* __restrict__ chars, const int* __restrict__ lengths,
      const float* __restrict__ Wf, const float* __restrict__ Wb,
      const float* __restrict__ bf, const float* __restrict__ bb){
    extern __shared__ char sm[];
    float* Wsm = (float*)(sm + XS_WS);   // [v][65]
    float* Os  = (float*)(sm + XS_OS);   // [g][129]
    int*   Cs  = (int*)  (sm + XS_CS);   // [b][16] (prescaled by 65)
    float* Fs  = (float*)(sm + XS_FS);   // [b][16]
    const int tid = threadIdx.x;
    const int gt = blockIdx.x, t = blockIdx.y, dir = blockIdx.z;
    const int g0 = gt * XT_G;
    const float* Wih = dir ? Wb : Wf;
    const float* bih = dir ? bb : bf;

    for (int i = tid; i < XT_G*V_; i += 256){
        int v = i & 127, gl = i >> 7;
        Wsm[v*65 + gl] = Wih[(g0 + gl)*V_ + v];
    }
    for (int i = tid; i < B_*W_; i += 256){
        int b = i >> 4, w = i & 15;
        int s = t;
        if (dir){ s = lengths[b] - 1 - t; if (s < 0) s = 0; }
        int bs = b*S_ + s;
        Cs[i] = chars[bs*W_ + w] * 65;
        Fs[i] = g_wt[bs*W_ + w];
    }
    __syncthreads();

    const int g = tid & 63, q = tid >> 6;
    const float bias = bih[g0 + g];
#pragma unroll
    for (int rr = 0; rr < 32; rr += 4){
        const int row = q*32 + rr;
        const int*   cr = Cs + row*16;
        const float* fr = Fs + row*16;
        float a0 = bias, a1 = bias, a2 = bias, a3 = bias;
#pragma unroll
        for (int w0 = 0; w0 < 16; w0 += 4){
            int4   c0 = *(const int4*)  (cr + w0);
            int4   c1 = *(const int4*)  (cr + 16 + w0);
            int4   c2 = *(const int4*)  (cr + 32 + w0);
            int4   c3 = *(const int4*)  (cr + 48 + w0);
            float4 f0 = *(const float4*)(fr + w0);
            float4 f1 = *(const float4*)(fr + 16 + w0);
            float4 f2 = *(const float4*)(fr + 32 + w0);
            float4 f3 = *(const float4*)(fr + 48 + w0);
            a0 = fmaf(f0.x, Wsm[c0.x + g], a0);
            a1 = fmaf(f1.x, Wsm[c1.x + g], a1);
            a2 = fmaf(f2.x, Wsm[c2.x + g], a2);
            a3 = fmaf(f3.x, Wsm[c3.x + g], a3);
            a0 = fmaf(f0.y, Wsm[c0.y + g], a0);
            a1 = fmaf(f1.y, Wsm[c1.y + g], a1);
            a2 = fmaf(f2.y, Wsm[c2.y + g], a2);
            a3 = fmaf(f3.y, Wsm[c3.y + g], a3);
            a0 = fmaf(f0.z, Wsm[c0.z + g], a0);
            a1 = fmaf(f1.z, Wsm[c1.z + g], a1);
            a2 = fmaf(f2.z, Wsm[c2.z + g], a2);
            a3 = fmaf(f3.z, Wsm[c3.z + g], a3);
            a0 = fmaf(f0.w, Wsm[c0.w + g], a0);
            a1 = fmaf(f1.w, Wsm[c1.w + g], a1);
            a2 = fmaf(f2.w, Wsm[c2.w + g], a2);
            a3 = fmaf(f3.w, Wsm[c3.w + g], a3);
        }
        Os[g*129 + row]     = a0;
        Os[g*129 + row + 1] = a1;
        Os[g*129 + row + 2] = a2;
        Os[g*129 + row + 3] = a3;
    }
    __syncthreads();

    float* dst = g_xw + ((size_t)(dir*S_ + t)*G3_ + g0)*B_;
    for (int i = tid; i < XT_G*B_; i += 256){
        int gl = i >> 7, b = i & 127;
        dst[gl*B_ + b] = Os[gl*129 + b];
    }
}

// ---------------- persistent recurrent kernel (HMMA + gates) ---------------
__global__ void __launch_bounds__(256)
k_step_pers(const int* __restrict__ lengths, const float* __restrict__ bhf,
            const float* __restrict__ bhb){
    extern __shared__ char sm[];
    const uint32_t sb = s2u(sm);
    const int tid  = threadIdx.x;
    const int lane = tid & 31;
    const int wid  = tid >> 5;
    const int wm = wid & 3, wn = wid >> 2;
    const int cu = blockIdx.x, bh = blockIdx.y, dir = blockIdx.z;
    const int grp = dir*2 + bh;

    for (int i = tid; i < 6144; i += 256){
        int p = i / 3072, j = i % 3072;
        int row = j >> 6, seg = j & 63;
        cpa16(sb + OFF_W + p*WPSZ + row*1040 + seg*16,
              &g_wp[p][dir][cu*48 + row][seg*8]);
    }
    asm volatile("cp.async.commit_group;");

    const int bloc = tid & 63, ub = tid >> 6;
    const int bg = bh*64 + bloc;
    const int mylen = lengths[bg];
    const int ubase = cu*16 + ub*4;
    const float* bhv = dir ? bhb : bhf;
    float bR[4], bZ[4], bN[4];
#pragma unroll
    for (int i = 0; i < 4; ++i){
        int u = ubase + i;
        bR[i] = bhv[u]; bZ[i] = bhv[H_ + u]; bN[i] = bhv[2*H_ + u];
    }
    float hreg[4] = {0.f, 0.f, 0.f, 0.f};

    const int ln = lane & 15;
    const uint32_t aoff = (uint32_t)(wm*16 + (lane & 15))*272 + (uint32_t)(lane >> 4)*16;
    const uint32_t boffr = (uint32_t)(wn*24 + (ln & 7))*1040 + (uint32_t)(ln >> 3)*16;
    float* Cs = (float*)(sm + OFF_C);

    asm volatile("cp.async.wait_group 0;");
    __syncthreads();

    for (int t = 0; t < S_; ++t){
        const int par = t & 1;

        float xr[4], xz[4], xn[4];
        {
            const float* xwb = g_xw + ((size_t)(dir*S_ + t))*G3_*B_;
#pragma unroll
            for (int i = 0; i < 4; ++i){
                int u = ubase + i;
                xr[i] = xwb[(size_t)u*B_ + bg];
                xz[i] = xwb[(size_t)(H_ + u)*B_ + bg];
                xn[i] = xwb[(size_t)(2*H_ + u)*B_ + bg];
            }
        }

#pragma unroll
        for (int c = 0; c < 2; ++c){
#pragma unroll
            for (int p = 0; p < 2; ++p)
#pragma unroll
                for (int j = 0; j < 4; ++j){
                    int i = tid + j*256;
                    int row = i >> 4, seg = i & 15;
                    cpa16(sb + OFF_A + (c*2 + p)*ASZ + row*272 + seg*16,
                          &g_hbf[par][dir][p][bh*64 + row][c*128 + seg*8]);
                }
            asm volatile("cp.async.commit_group;");
        }

        float acc[3][4] = {};
        for (int c = 0; c < 4; ++c){
            if (c < 3) asm volatile("cp.async.wait_group 1;");
            else       asm volatile("cp.async.wait_group 0;");
            __syncthreads();
            const int buf = c & 1;
            const uint32_t Ah = sb + OFF_A + (buf*2)*ASZ + aoff;
            const uint32_t Al = Ah + ASZ;
            const uint32_t Bb = sb + OFF_W + boffr + (uint32_t)c*256;
#pragma unroll
            for (int ks = 0; ks < 8; ++ks){
                uint32_t aH[4], aL[4];
                ldsm4(aH, Ah + ks*32);
                ldsm4(aL, Al + ks*32);
#pragma unroll
                for (int nt = 0; nt < 3; ++nt){
                    uint32_t bHr[2], bLr[2];
                    uint32_t ba = Bb + (uint32_t)nt*8*1040 + (uint32_t)ks*32;
                    ldsm2(bHr, ba);
                    ldsm2(bLr, ba + WPSZ);
                    mma16816(acc[nt], aH, bHr);
                    mma16816(acc[nt], aL, bHr);
                    mma16816(acc[nt], aH, bLr);
                }
            }
            __syncthreads();
            if (c < 2){
#pragma unroll
                for (int p = 0; p < 2; ++p)
#pragma unroll
                    for (int j = 0; j < 4; ++j){
                        int i = tid + j*256;
                        int row = i >> 4, seg = i & 15;
                        cpa16(sb + OFF_A + (buf*2 + p)*ASZ + row*272 + seg*16,
                              &g_hbf[par][dir][p][bh*64 + row][(c+2)*128 + seg*8]);
                    }
                asm volatile("cp.async.commit_group;");
            }
        }

        {
            const int trow = lane >> 2, tcol = (lane & 3)*2;
#pragma unroll
            for (int nt = 0; nt < 3; ++nt){
                int n = wn*24 + nt*8 + tcol;
                int m = wm*16 + trow;
                Cs[n*68 + m]          = acc[nt][0];
                Cs[(n+1)*68 + m]      = acc[nt][1];
                Cs[n*68 + m + 8]      = acc[nt][2];
                Cs[(n+1)*68 + m + 8]  = acc[nt][3];
            }
        }
        __syncthreads();

        {
            const bool msk = (t < mylen);
            const int par2 = par ^ 1;
            __nv_bfloat16 ohi[4], olo[4];
#pragma unroll
            for (int i = 0; i < 4; ++i){
                const int ul = ub*4 + i;
                float pr = Cs[(ul*3+0)*68 + bloc] + bR[i] + xr[i];
                float pz = Cs[(ul*3+1)*68 + bloc] + bZ[i] + xz[i];
                float pn = Cs[(ul*3+2)*68 + bloc] + bN[i];
                float r = fsig(pr);
                float z = fsig(pz);
                float n = ftanh(xn[i] + r*pn);
                float hnew = (1.f - z)*n + z*hreg[i];
                float gv = msk ? hnew : 0.f;
                if (msk) hreg[i] = hnew;
                ohi[i] = __float2bfloat16(gv);
                olo[i] = __float2bfloat16(gv - __bfloat162float(ohi[i]));
            }
            *(uint2*)&g_gb[0][dir][t][bg][ubase] = *(uint2*)ohi;
            *(uint2*)&g_gb[1][dir][t][bg][ubase] = *(uint2*)olo;
            __nv_bfloat16 hi[4], lo[4];
#pragma unroll
            for (int i = 0; i < 4; ++i){
                hi[i] = __float2bfloat16(hreg[i]);
                lo[i] = __float2bfloat16(hreg[i] - __bfloat162float(hi[i]));
            }
            *(uint2*)&g_hbf[par2][dir][0][bg][ubase] = *(uint2*)hi;
            *(uint2*)&g_hbf[par2][dir][1][bg][ubase] = *(uint2*)lo;
        }

        // quadrant-local barrier: 32 CTAs, release/acquire (cg grid-sync pattern)
        __syncthreads();
        if (tid == 0){
            asm volatile("red.release.gpu.global.add.s32 [%0], 1;"
                         :: "l"(&g_bar4[grp]) : "memory");
            const int target = 32*(t+1);
            int v;
            do {
                asm volatile("ld.global.acquire.gpu.b32 %0, [%1];" : "=r"(v) : "l"(&g_bar4[grp]));
            } while (v < target);
        }
        __syncthreads();
    }
}

// ---------------- final linear via HMMA (3-term split bf16) ----------------
__global__ void __launch_bounds__(256)
k_lin_mma(const int* __restrict__ lengths, const float* __restrict__ blin,
          float* __restrict__ out){
    extern __shared__ char sm[];
    const uint32_t sb = s2u(sm);
    const int tid  = threadIdx.x;
    const int lane = tid & 31;
    const int wid  = tid >> 5;
    const int wm = wid & 3, wn = wid >> 2;       // m 16-tile, n 32-half
    const int r0 = blockIdx.x * 64;

    __shared__ const __nv_bfloat16* pF[2][64];
    __shared__ const __nv_bfloat16* pB[2][64];
    if (tid < 128){
        int p = tid >> 6, row = tid & 63;
        int r = r0 + row;
        int b = r >> 7, s = r & 127;
        pF[p][row] = &g_gb[p][0][s][b][0];
        int len = lengths[b];
        pB[p][row] = (s < len) ? &g_gb[p][1][len-1-s][b][0]
                               : (const __nv_bfloat16*)g_zbuf;
    }
    __syncthreads();

    // fill chunk c into buffer buf (A rows + B rows, both precisions)
    auto fill = [&](int c, int buf){
#pragma unroll
        for (int p = 0; p < 2; ++p){
            uint32_t Abase = sb + LOFF_A + (buf*2 + p)*LASZ;
#pragma unroll
            for (int j = 0; j < 4; ++j){
                int i = tid + j*256;
                int row = i >> 4, seg = i & 15;
                const __nv_bfloat16* src = (c < 4)
                    ? pF[p][row] + c*128 + seg*8
                    : pB[p][row] + ((pB[p][row] == (const __nv_bfloat16*)g_zbuf) ? seg*8
                                    : (c-4)*128 + seg*8);
                cpa16(Abase + row*272 + seg*16, src);
            }
            uint32_t Bbase = sb + LOFF_B + (buf*2 + p)*LASZ;
#pragma unroll
            for (int j = 0; j < 4; ++j){
                int i = tid + j*256;
                int n = i >> 4, seg = i & 15;
                cpa16(Bbase + n*272 + seg*16, &g_wlb[p][n][c*128 + seg*8]);
            }
        }
        asm volatile("cp.async.commit_group;");
    };

    fill(0, 0);
    fill(1, 1);

    const int ln = lane & 15;
    const uint32_t aoff = (uint32_t)(wm*16 + (lane & 15))*272 + (uint32_t)(lane >> 4)*16;
    const uint32_t boff = (uint32_t)(wn*32 + (ln & 7))*272 + (uint32_t)(ln >> 3)*16;
    float acc[4][4] = {};

    for (int c = 0; c < 8; ++c){
        if (c < 6) asm volatile("cp.async.wait_group 1;");
        else       asm volatile("cp.async.wait_group 0;");
        __syncthreads();
        const int buf = c & 1;
        const uint32_t Ah = sb + LOFF_A + (buf*2)*LASZ + aoff;
        const uint32_t Al = Ah + LASZ;
        const uint32_t Bh = sb + LOFF_B + (buf*2)*LASZ + boff;
        const uint32_t Bl = Bh + LASZ;
#pragma unroll
        for (int ks = 0; ks < 8; ++ks){
            uint32_t aH[4], aL[4];
            ldsm4(aH, Ah + ks*32);
            ldsm4(aL, Al + ks*32);
#pragma unroll
            for (int nt = 0; nt < 4; ++nt){
                uint32_t bH[2], bL[2];
                ldsm2(bH, Bh + (uint32_t)nt*8*272 + (uint32_t)ks*32);
                ldsm2(bL, Bl + (uint32_t)nt*8*272 + (uint32_t)ks*32);
                mma16816(acc[nt], aH, bH);
                mma16816(acc[nt], aL, bH);
                mma16816(acc[nt], aH, bL);
            }
        }
        __syncthreads();
        if (c < 6) fill(c + 2, buf);
    }

    float* Cs = (float*)(sm + LOFF_C);   // [n 64][m 68]
    {
        const int trow = lane >> 2, tcol = (lane & 3)*2;
#pragma unroll
        for (int nt = 0; nt < 4; ++nt){
            int n = wn*32 + nt*8 + tcol;
            int m = wm*16 + trow;
            Cs[n*68 + m]          = acc[nt][0];
            Cs[(n+1)*68 + m]      = acc[nt][1];
            Cs[n*68 + m + 8]      = acc[nt][2];
            Cs[(n+1)*68 + m + 8]  = acc[nt][3];
        }
    }
    __syncthreads();

    {
        const int row = tid & 63, lq = tid >> 6;
        float* dst = out + (size_t)(r0 + row)*L_;
#pragma unroll
        for (int j = 0; j < 4; ++j){
            int l = lq*16 + j*4;
            float4 v;
            v.x = Cs[(l+0)*68 + row] + blin[l+0];
            v.y = Cs[(l+1)*68 + row] + blin[l+1];
            v.z = Cs[(l+2)*68 + row] + blin[l+2];
            v.w = Cs[(l+3)*68 + row] + blin[l+3];
            *(float4*)(dst + l) = v;
        }
    }
}

// ---------------- launch ----------------
extern "C" void kernel_launch(void* const* d_in, const int* in_sizes, int n_in,
                              void* d_out, int out_size) {
    const int*   chars   = (const int*)  d_in[0];
    const int*   lengths = (const int*)  d_in[1];
    const float* forget  = (const float*)d_in[2];
    const float* W_ih_f  = (const float*)d_in[3];
    const float* W_hh_f  = (const float*)d_in[4];
    const float* b_ih_f  = (const float*)d_in[5];
    const float* b_hh_f  = (const float*)d_in[6];
    const float* W_ih_b  = (const float*)d_in[7];
    const float* W_hh_b  = (const float*)d_in[8];
    const float* b_ih_b  = (const float*)d_in[9];
    const float* b_hh_b  = (const float*)d_in[10];
    const float* W_lin   = (const float*)d_in[11];
    const float* b_lin   = (const float*)d_in[12];
    float* out = (float*)d_out;

    cudaFuncSetAttribute(k_step_pers, cudaFuncAttributeMaxDynamicSharedMemorySize, STEP_SMEM);
    cudaFuncSetAttribute(k_xws, cudaFuncAttributeMaxDynamicSharedMemorySize, XS_SMEM);
    cudaFuncSetAttribute(k_lin_mma, cudaFuncAttributeMaxDynamicSharedMemorySize, LIN_SMEM);

    k_zero <<<1024, 256>>>();
    k_prep <<<(2*G3_*H_ + 255)/256, 256>>>(W_hh_f, W_hh_b);
    k_prepL<<<(L_*2*H_ + 255)/256, 256>>>(W_lin);
    k_wts  <<<(B_*S_ + 255)/256, 256>>>(chars, forget);
    k_xws  <<<dim3(G3_/XT_G, S_, 2), 256, XS_SMEM>>>(chars, lengths, W_ih_f, W_ih_b, b_ih_f, b_ih_b);
    k_step_pers<<<dim3(32, 2, 2), 256, STEP_SMEM>>>(lengths, b_hh_f, b_hh_b);
    k_lin_mma<<<(S_*B_)/64, 256, LIN_SMEM>>>(lengths, b_lin, out);
}